// round 12
// baseline (speedup 1.0000x reference)
#include <cuda_runtime.h>
#include <cstdint>

#define B_    4
#define T_    1024
#define DIM_  512
#define POOL_ 64
#define K_    50

#define C1_END 304   // chunk 1: tokens [0,304) (includes all t<64)
#define C2_END 664   // chunk 2: [304,664); chunk 3: [664,1024)

// Scratch (device globals: allocation-free per harness rules)
__device__ __align__(16) float g_y[B_ * POOL_ * POOL_];   // y[b][t<64][p]
__device__ int   g_idx[T_ * K_];                          // top-50 indices per t
__device__ __align__(16) float g_z[B_ * POOL_ * DIM_];    // z[b][j][d]

// packed fp32x2 ops (Blackwell FFMA2 — only reachable via PTX)
#define FMA2(d, a, b) \
    asm("fma.rn.f32x2 %0, %1, %2, %3;" : "=l"(d) : "l"(a), "l"(b), "l"(d))
#define ADD2(d, a, b) \
    asm("add.rn.f32x2 %0, %1, %2;" : "=l"(d) : "l"(a), "l"(b))
#define UNPACK2(lo, hi, v) \
    asm("mov.b64 {%0, %1}, %2;" : "=f"(lo), "=f"(hi) : "l"(v))
#define LDS_V2U64(a0, a1, addr) \
    asm("ld.shared.v2.b64 {%0, %1}, [%2];" : "=l"(a0), "=l"(a1) : "r"(addr))

// ---------------------------------------------------------------------------
// Kernel 1 (TK=1): one token per block, block = 256.
// f32x2 lanes = POOL PAIRS (r7 layout); x staged lane-duplicated in smem.
// Thread (dc=tid>>4, pg=tid&15): pools pg*4..pg*4+3 for 4 batches over dims
// [dc*32, dc*32+32). Butterfly + smem reduce, LN + stable top-50 tail.
// Half the per-block work of TK=2 -> short critical path for the prefix.
// ---------------------------------------------------------------------------
__global__ __launch_bounds__(256) void k1_tok(
        const float* __restrict__ x,
        const float* __restrict__ w1,
        const float* __restrict__ b1,
        const float* __restrict__ g1,
        const float* __restrict__ bt1,
        int t_off) {
    __shared__ __align__(16) float2 xs2[B_ * DIM_];       // 16KB dup x
    __shared__ float partial[8 * B_ * POOL_];             // 8KB
    __shared__ float sv[POOL_];
    __shared__ float wsum[2][B_], wsq[2][B_];

    const int t   = t_off + blockIdx.x;
    const int tid = threadIdx.x;
    const int pg  = tid & 15;
    const int dc  = tid >> 4;

    uint32_t sx;
    asm("{ .reg .u64 tt; cvta.to.shared.u64 tt, %1; cvt.u32.u64 %0, tt; }"
        : "=r"(sx) : "l"(xs2));

    // ---- load x row per batch, lane-duplicated ----
    #pragma unroll
    for (int i = tid; i < B_ * (DIM_ / 4); i += 256) {
        int b = i >> 7, j = i & 127;
        float4 v = reinterpret_cast<const float4*>(
            x + ((size_t)b * T_ + t) * DIM_)[j];
        float2* d = xs2 + b * DIM_ + j * 4;
        d[0] = make_float2(v.x, v.x);
        d[1] = make_float2(v.y, v.y);
        d[2] = make_float2(v.z, v.z);
        d[3] = make_float2(v.w, v.w);
    }
    __syncthreads();

    // ---- main loop: 32 dims x 4 batches x 2 pool-pairs ----
    unsigned long long acc[B_][2] = {};
    const ulonglong2* wp = reinterpret_cast<const ulonglong2*>(w1)
                           + (size_t)(dc * 32) * 16 + pg;

    #pragma unroll 4
    for (int d2 = 0; d2 < 16; d2++) {
        ulonglong2 wd0 = __ldg(wp + d2 * 32);        // dim dc*32 + 2*d2
        ulonglong2 wd1 = __ldg(wp + d2 * 32 + 16);   // dim +1
        const uint32_t a = sx + (uint32_t)((dc * 32 + d2 * 2) * 8);
        #pragma unroll
        for (int b = 0; b < B_; b++) {
            unsigned long long xv0, xv1;
            LDS_V2U64(xv0, xv1, a + (uint32_t)(b * DIM_ * 8));
            FMA2(acc[b][0], xv0, wd0.x);
            FMA2(acc[b][1], xv0, wd0.y);
            FMA2(acc[b][0], xv1, wd1.x);
            FMA2(acc[b][1], xv1, wd1.y);
        }
    }

    // ---- reduce over dc: butterfly (dc pairs), then smem ----
    #pragma unroll
    for (int b = 0; b < B_; b++) {
        #pragma unroll
        for (int pr = 0; pr < 2; pr++) {
            unsigned long long o = __shfl_xor_sync(0xffffffffu, acc[b][pr], 16);
            ADD2(acc[b][pr], acc[b][pr], o);
        }
    }
    __syncthreads();   // x reads done (xs2 untouched after; partial separate)

    if ((tid & 16) == 0) {
        const int w = tid >> 5;
        #pragma unroll
        for (int b = 0; b < B_; b++) {
            #pragma unroll
            for (int pr = 0; pr < 2; pr++) {
                float lo, hi;
                UNPACK2(lo, hi, acc[b][pr]);
                partial[w * 256 + b * 64 + pg * 4 + pr * 2 + 0] = lo;
                partial[w * 256 + b * 64 + pg * 4 + pr * 2 + 1] = hi;
            }
        }
    }
    __syncthreads();

    // ---- tail on first 64 threads (warps 0,1): pp = tid ----
    if (tid < POOL_) {
        const int pp = tid;
        const float bias = b1[pp];

        float vv[B_];
        #pragma unroll
        for (int b = 0; b < B_; b++) {
            float a = bias;
            #pragma unroll
            for (int w = 0; w < 8; w++)
                a += partial[w * 256 + b * 64 + pp];
            vv[b] = fmaxf(a, 0.f);
        }

        float s[B_], q[B_];
        #pragma unroll
        for (int b = 0; b < B_; b++) { s[b] = vv[b]; q[b] = vv[b] * vv[b]; }
        #pragma unroll
        for (int off = 16; off > 0; off >>= 1) {
            #pragma unroll
            for (int b = 0; b < B_; b++) {
                s[b] += __shfl_xor_sync(0xffffffffu, s[b], off);
                q[b] += __shfl_xor_sync(0xffffffffu, q[b], off);
            }
        }
        const int w = tid >> 5;   // 0 or 1
        if ((tid & 31) == 0) {
            #pragma unroll
            for (int b = 0; b < B_; b++) { wsum[w][b] = s[b]; wsq[w][b] = q[b]; }
        }
        __syncwarp();
        asm volatile("bar.sync 1, 64;" ::: "memory");

        const float gp = g1[pp], bp = bt1[pp];
        float ysum = 0.f;
        float yv[B_];
        #pragma unroll
        for (int b = 0; b < B_; b++) {
            float S = wsum[0][b] + wsum[1][b];
            float Q = wsq[0][b]  + wsq[1][b];
            float m   = S * (1.f / POOL_);
            float var = Q * (1.f / POOL_) - m * m;
            float r   = rsqrtf(var + 1e-5f);
            yv[b] = (vv[b] - m) * r * gp + bp;
            ysum += yv[b];
        }

        if (t < POOL_) {
            #pragma unroll
            for (int b = 0; b < B_; b++)
                g_y[(b * POOL_ + t) * POOL_ + pp] = yv[b];
        }

        sv[pp] = ysum;
        asm volatile("bar.sync 1, 64;" ::: "memory");

        const float mine = ysum;
        int rank = 0;
        #pragma unroll
        for (int j = 0; j < POOL_; j++) {
            float o = sv[j];
            rank += (o > mine) || ((o == mine) && (j < pp));
        }
        if (rank < K_) g_idx[t * K_ + rank] = pp;
    }
}

// ---------------------------------------------------------------------------
// Kernel 2: z[b,j,:] = LN(relu(y[b,j,:] @ w2 + b2))   (256 distinct rows)
// ---------------------------------------------------------------------------
__global__ void k2_expand(const float* __restrict__ w2,
                          const float* __restrict__ b2,
                          const float* __restrict__ g2,
                          const float* __restrict__ bt2) {
    const int bj = blockIdx.x;
    const int d  = threadIdx.x;

    __shared__ float yr[POOL_];
    if (d < POOL_) yr[d] = g_y[bj * POOL_ + d];
    __syncthreads();

    float acc = b2[d];
    #pragma unroll
    for (int p = 0; p < POOL_; p++)
        acc += yr[p] * w2[p * DIM_ + d];

    float v = fmaxf(acc, 0.f);

    float s = v, q = v * v;
    #pragma unroll
    for (int off = 16; off > 0; off >>= 1) {
        s += __shfl_xor_sync(0xffffffffu, s, off);
        q += __shfl_xor_sync(0xffffffffu, q, off);
    }
    __shared__ float ps[16], pq[16];
    const int w = d >> 5;
    if ((d & 31) == 0) { ps[w] = s; pq[w] = q; }
    __syncthreads();
    float S = 0.f, Q = 0.f;
    #pragma unroll
    for (int i = 0; i < 16; i++) { S += ps[i]; Q += pq[i]; }

    float m   = S * (1.f / DIM_);
    float var = Q * (1.f / DIM_) - m * m;
    g_z[bj * DIM_ + d] = (v - m) * rsqrtf(var + 1e-5f) * g2[d] + bt2[d];
}

// ---------------------------------------------------------------------------
// Kernel 3: out[b,t,k,:] = z[b, idx[t,k], :] for tokens [t_lo, ...).
// Warp-per-row float4 copies; z via __ldg (L1/L2-hot), output via __stcs.
// grid = n_tok*B_*K_/64, block = 512 (64 rows/block).
// ---------------------------------------------------------------------------
__global__ void k3_gather(float* __restrict__ out, int t_lo) {
    const int warp = threadIdx.x >> 5;
    const int lane = threadIdx.x & 31;
    const unsigned base = blockIdx.x * 64u;

    #pragma unroll
    for (int i = 0; i < 4; i++) {
        unsigned rr  = base + warp + i * 16;         // local row
        unsigned tt  = rr / (unsigned)(B_ * K_);     // local token
        unsigned rem = rr - tt * (unsigned)(B_ * K_);
        unsigned b   = rem / K_;
        unsigned k   = rem - b * K_;
        unsigned t   = t_lo + tt;
        int j = g_idx[t * K_ + k];

        const float4* src = reinterpret_cast<const float4*>(g_z)
                            + (size_t)(b * POOL_ + j) * (DIM_ / 4);
        float4* dst = reinterpret_cast<float4*>(out)
                      + ((size_t)((b * T_ + t) * K_) + k) * (DIM_ / 4);
        #pragma unroll
        for (int cc = 0; cc < 4; cc++) {
            float4 v = __ldg(src + lane + 32 * cc);
            __stcs(dst + lane + 32 * cc, v);
        }
    }
}

// ---------------------------------------------------------------------------
// Fork/join resources — created once at load time (host-side only).
// ---------------------------------------------------------------------------
namespace {
cudaStream_t g_s2 = nullptr;
cudaEvent_t  g_eA = nullptr, g_eB2 = nullptr, g_eB3 = nullptr;
struct StreamInit {
    StreamInit() {
        if (cudaStreamCreateWithFlags(&g_s2, cudaStreamNonBlocking) != cudaSuccess)
            g_s2 = nullptr;
        if (cudaEventCreateWithFlags(&g_eA,  cudaEventDisableTiming) != cudaSuccess)
            g_eA = nullptr;
        if (cudaEventCreateWithFlags(&g_eB2, cudaEventDisableTiming) != cudaSuccess)
            g_eB2 = nullptr;
        if (cudaEventCreateWithFlags(&g_eB3, cudaEventDisableTiming) != cudaSuccess)
            g_eB3 = nullptr;
    }
} g_stream_init;
}

// ---------------------------------------------------------------------------
extern "C" void kernel_launch(void* const* d_in, const int* in_sizes, int n_in,
                              void* d_out, int out_size) {
    const float* x   = (const float*)d_in[0];
    const float* w1  = (const float*)d_in[1];
    const float* b1  = (const float*)d_in[2];
    const float* g1  = (const float*)d_in[3];
    const float* bt1 = (const float*)d_in[4];
    const float* w2  = (const float*)d_in[5];
    const float* b2  = (const float*)d_in[6];
    const float* g2  = (const float*)d_in[7];
    const float* bt2 = (const float*)d_in[8];
    float* out = (float*)d_out;

    const int n1 = C1_END;            // 304
    const int n2 = C2_END - C1_END;   // 360
    const int n3 = T_ - C2_END;       // 360

    if (g_s2 && g_eA && g_eB2 && g_eB3) {
        // ---- critical path: k1c1 (includes t<64) -> k2 -> k3 chunk 1 ----
        k1_tok<<<n1, 256>>>(x, w1, b1, g1, bt1, 0);
        cudaEventRecord(g_eA, 0);

        // ---- side stream: remaining k1 chunks, hidden under the gathers ----
        cudaStreamWaitEvent(g_s2, g_eA, 0);
        k1_tok<<<n2, 256, 0, g_s2>>>(x, w1, b1, g1, bt1, C1_END);
        cudaEventRecord(g_eB2, g_s2);
        k1_tok<<<n3, 256, 0, g_s2>>>(x, w1, b1, g1, bt1, C2_END);
        cudaEventRecord(g_eB3, g_s2);

        // ---- main stream continues ----
        k2_expand<<<B_ * POOL_, DIM_>>>(w2, b2, g2, bt2);
        k3_gather<<<(n1 * B_ * K_) / 64, 512>>>(out, 0);
        cudaStreamWaitEvent(0, g_eB2, 0);
        k3_gather<<<(n2 * B_ * K_) / 64, 512>>>(out, C1_END);
        cudaStreamWaitEvent(0, g_eB3, 0);
        k3_gather<<<(n3 * B_ * K_) / 64, 512>>>(out, C2_END);
    } else {
        // sequential fallback
        k1_tok<<<T_, 256>>>(x, w1, b1, g1, bt1, 0);
        k2_expand<<<B_ * POOL_, DIM_>>>(w2, b2, g2, bt2);
        k3_gather<<<(T_ * B_ * K_) / 64, 512>>>(out, 0);
    }
}

// round 13
// speedup vs baseline: 1.0609x; 1.0609x over previous
#include <cuda_runtime.h>
#include <cstdint>

#define B_    4
#define T_    1024
#define DIM_  512
#define POOL_ 64
#define K_    50
#define TK_   2      // tokens per k1 block (packed in f32x2)

// Scratch (device globals: allocation-free per harness rules)
__device__ __align__(16) float g_y[B_ * POOL_ * POOL_];   // y[b][t<64][p]
__device__ int   g_idx[T_ * K_];                          // top-50 indices per t
__device__ __align__(16) float g_z[B_ * POOL_ * DIM_];    // z[b][j][d]

// packed fp32x2 ops (Blackwell FFMA2 — only reachable via PTX)
#define FMA2(d, a, b) \
    asm("fma.rn.f32x2 %0, %1, %2, %3;" : "=l"(d) : "l"(a), "l"(b), "l"(d))
#define ADD2(d, a, b) \
    asm("add.rn.f32x2 %0, %1, %2;" : "=l"(d) : "l"(a), "l"(b))
#define UNPACK2(lo, hi, v) \
    asm("mov.b64 {%0, %1}, %2;" : "=f"(lo), "=f"(hi) : "l"(v))
#define LDS_V2U64(a0, a1, addr) \
    asm("ld.shared.v2.b64 {%0, %1}, [%2];" : "=l"(a0), "=l"(a1) : "r"(addr))

// ---------------------------------------------------------------------------
// Kernel 1 (round-5 best config, byte-identical): 2 tokens/block, grid=512,
// block=256. f32x2 lanes = POOL PAIRS; x staged lane-duplicated in smem.
// Thread (dc=tid>>4, pg=tid&15): pools pg*4..pg*4+3, 8 (b,tok) rows,
// dims [dc*32, dc*32+32). Butterfly + smem reduce, LN + stable top-50 tail.
// ---------------------------------------------------------------------------
__global__ __launch_bounds__(256) void k1_reduce_topk(
        const float* __restrict__ x,
        const float* __restrict__ w1,
        const float* __restrict__ b1,
        const float* __restrict__ g1,
        const float* __restrict__ bt1) {
    __shared__ __align__(16) float2 pool2[B_ * TK_ * DIM_];  // 32KB
    __shared__ float sv[TK_ * POOL_];
    __shared__ float wsum[4][B_], wsq[4][B_];
    float* poolf = reinterpret_cast<float*>(pool2);

    const int t0  = blockIdx.x * TK_;
    const int tid = threadIdx.x;
    const int pg  = tid & 15;
    const int dc  = tid >> 4;

    uint32_t sx;
    asm("{ .reg .u64 t; cvta.to.shared.u64 t, %1; cvt.u32.u64 %0, t; }"
        : "=r"(sx) : "l"(pool2));

    // ---- phase 1: load x rows, lane-duplicated ----
    #pragma unroll
    for (int i = tid; i < B_ * (DIM_ / 4); i += 256) {
        int b = i >> 7, j = i & 127;
        const float* xb = x + ((size_t)b * T_ + t0) * DIM_;
        float4 v0 = reinterpret_cast<const float4*>(xb)[j];
        float4 v1 = reinterpret_cast<const float4*>(xb + DIM_)[j];
        float2* d0 = pool2 + (b * 2 + 0) * DIM_ + j * 4;
        d0[0] = make_float2(v0.x, v0.x);
        d0[1] = make_float2(v0.y, v0.y);
        d0[2] = make_float2(v0.z, v0.z);
        d0[3] = make_float2(v0.w, v0.w);
        float2* d1 = pool2 + (b * 2 + 1) * DIM_ + j * 4;
        d1[0] = make_float2(v1.x, v1.x);
        d1[1] = make_float2(v1.y, v1.y);
        d1[2] = make_float2(v1.z, v1.z);
        d1[3] = make_float2(v1.w, v1.w);
    }
    __syncthreads();

    // ---- main loop: 32 dims x 8 (b,tok) rows x 2 pool-pairs ----
    unsigned long long acc[8][2] = {};
    const ulonglong2* w1q = reinterpret_cast<const ulonglong2*>(w1);

    #pragma unroll 4
    for (int d2 = 0; d2 < 16; d2++) {
        const int d = dc * 32 + d2 * 2;
        ulonglong2 wd0 = __ldg(w1q + (size_t)d * 16 + pg);
        ulonglong2 wd1 = __ldg(w1q + (size_t)(d + 1) * 16 + pg);
        #pragma unroll
        for (int bt = 0; bt < 8; bt++) {
            unsigned long long xv0, xv1;
            LDS_V2U64(xv0, xv1, sx + (uint32_t)((bt * DIM_ + d) * 8));
            FMA2(acc[bt][0], xv0, wd0.x);
            FMA2(acc[bt][1], xv0, wd0.y);
            FMA2(acc[bt][0], xv1, wd1.x);
            FMA2(acc[bt][1], xv1, wd1.y);
        }
    }

    // ---- reduce over dc: butterfly (dc pairs), then smem ----
    #pragma unroll
    for (int bt = 0; bt < 8; bt++) {
        #pragma unroll
        for (int pr = 0; pr < 2; pr++) {
            unsigned long long o = __shfl_xor_sync(0xffffffffu, acc[bt][pr], 16);
            ADD2(acc[bt][pr], acc[bt][pr], o);
        }
    }
    __syncthreads();   // all x reads done; reuse poolf for partials

    if ((tid & 16) == 0) {
        const int w = tid >> 5;
        #pragma unroll
        for (int bt = 0; bt < 8; bt++) {
            #pragma unroll
            for (int pr = 0; pr < 2; pr++) {
                float lo, hi;
                UNPACK2(lo, hi, acc[bt][pr]);
                poolf[w * 512 + bt * 64 + pg * 4 + pr * 2 + 0] = lo;
                poolf[w * 512 + bt * 64 + pg * 4 + pr * 2 + 1] = hi;
            }
        }
    }
    __syncthreads();

    // ---- tail on first 128 threads: tk = tid>>6, pp = tid&63 ----
    float vv[B_];
    if (tid < TK_ * POOL_) {
        const int tk = tid >> 6;
        const int pp = tid & 63;
        const float bias = b1[pp];
        #pragma unroll
        for (int b = 0; b < B_; b++) {
            float a = bias;
            #pragma unroll
            for (int w = 0; w < 8; w++)
                a += poolf[w * 512 + (b * TK_ + tk) * 64 + pp];
            vv[b] = fmaxf(a, 0.f);
        }
        float s[B_], q[B_];
        #pragma unroll
        for (int b = 0; b < B_; b++) { s[b] = vv[b]; q[b] = vv[b] * vv[b]; }
        #pragma unroll
        for (int off = 16; off > 0; off >>= 1) {
            #pragma unroll
            for (int b = 0; b < B_; b++) {
                s[b] += __shfl_xor_sync(0xffffffffu, s[b], off);
                q[b] += __shfl_xor_sync(0xffffffffu, q[b], off);
            }
        }
        const int w = tid >> 5;
        if ((tid & 31) == 0) {
            #pragma unroll
            for (int b = 0; b < B_; b++) { wsum[w][b] = s[b]; wsq[w][b] = q[b]; }
        }
    }
    __syncthreads();

    if (tid < TK_ * POOL_) {
        const int tk = tid >> 6;
        const int pp = tid & 63;
        const int t  = t0 + tk;
        const float gp = g1[pp], bp = bt1[pp];

        float ysum = 0.f;
        float yv[B_];
        #pragma unroll
        for (int b = 0; b < B_; b++) {
            float S = wsum[tk * 2][b] + wsum[tk * 2 + 1][b];
            float Q = wsq[tk * 2][b]  + wsq[tk * 2 + 1][b];
            float m   = S * (1.f / POOL_);
            float var = Q * (1.f / POOL_) - m * m;
            float r   = rsqrtf(var + 1e-5f);
            yv[b] = (vv[b] - m) * r * gp + bp;
            ysum += yv[b];
        }

        if (t < POOL_) {
            #pragma unroll
            for (int b = 0; b < B_; b++)
                g_y[(b * POOL_ + t) * POOL_ + pp] = yv[b];
        }

        sv[tk * POOL_ + pp] = ysum;
        __syncwarp();
        asm volatile("bar.sync 1, 128;" ::: "memory");

        const float mine = ysum;
        int rank = 0;
        #pragma unroll
        for (int j = 0; j < POOL_; j++) {
            float o = sv[tk * POOL_ + j];
            rank += (o > mine) || ((o == mine) && (j < pp));
        }
        if (rank < K_) g_idx[t * K_ + rank] = pp;
    }
}

// ---------------------------------------------------------------------------
// Kernel 2: z[b,j,:] = LN(relu(y[b,j,:] @ w2 + b2))   (256 distinct rows)
// grid = B_*POOL_, block = 512
// ---------------------------------------------------------------------------
__global__ void k2_expand(const float* __restrict__ w2,
                          const float* __restrict__ b2,
                          const float* __restrict__ g2,
                          const float* __restrict__ bt2) {
    const int bj = blockIdx.x;
    const int d  = threadIdx.x;

    __shared__ float yr[POOL_];
    if (d < POOL_) yr[d] = g_y[bj * POOL_ + d];
    __syncthreads();

    float acc = b2[d];
    #pragma unroll
    for (int p = 0; p < POOL_; p++)
        acc += yr[p] * w2[p * DIM_ + d];

    float v = fmaxf(acc, 0.f);

    float s = v, q = v * v;
    #pragma unroll
    for (int off = 16; off > 0; off >>= 1) {
        s += __shfl_xor_sync(0xffffffffu, s, off);
        q += __shfl_xor_sync(0xffffffffu, q, off);
    }
    __shared__ float ps[16], pq[16];
    const int w = d >> 5;
    if ((d & 31) == 0) { ps[w] = s; pq[w] = q; }
    __syncthreads();
    float S = 0.f, Q = 0.f;
    #pragma unroll
    for (int i = 0; i < 16; i++) { S += ps[i]; Q += pq[i]; }

    float m   = S * (1.f / DIM_);
    float var = Q * (1.f / DIM_) - m * m;
    g_z[bj * DIM_ + d] = (v - m) * rsqrtf(var + 1e-5f) * g2[d] + bt2[d];
}

// ---------------------------------------------------------------------------
// Kernel 3: out[b,t,k,:] = z[b, idx[t,k], :]  — the 419 MB write stream.
// CHANGE vs round 5: z reads via __ldcg (L2-cached, L1-BYPASS) so the L1
// pipe carries only the store stream; stores stay __stcs (streaming).
// grid = 3200, block = 512 (64 rows/block, warp-per-row float4).
// ---------------------------------------------------------------------------
__global__ void k3_gather(float* __restrict__ out) {
    const int warp = threadIdx.x >> 5;
    const int lane = threadIdx.x & 31;
    const unsigned base = blockIdx.x * 64u;

    #pragma unroll
    for (int i = 0; i < 4; i++) {
        unsigned r   = base + warp + i * 16;
        unsigned b   = r / (unsigned)(T_ * K_);
        unsigned rem = r - b * (unsigned)(T_ * K_);
        unsigned t   = rem / K_;
        unsigned k   = rem - t * K_;
        int j = g_idx[t * K_ + k];

        const float4* src = reinterpret_cast<const float4*>(g_z)
                            + (size_t)(b * POOL_ + j) * (DIM_ / 4);
        float4* dst = reinterpret_cast<float4*>(out)
                      + (size_t)r * (DIM_ / 4);
        #pragma unroll
        for (int cc = 0; cc < 4; cc++) {
            float4 v = __ldcg(src + lane + 32 * cc);   // L2-cached, skip L1
            __stcs(dst + lane + 32 * cc, v);
        }
    }
}

// ---------------------------------------------------------------------------
extern "C" void kernel_launch(void* const* d_in, const int* in_sizes, int n_in,
                              void* d_out, int out_size) {
    const float* x   = (const float*)d_in[0];
    const float* w1  = (const float*)d_in[1];
    const float* b1  = (const float*)d_in[2];
    const float* g1  = (const float*)d_in[3];
    const float* bt1 = (const float*)d_in[4];
    const float* w2  = (const float*)d_in[5];
    const float* b2  = (const float*)d_in[6];
    const float* g2  = (const float*)d_in[7];
    const float* bt2 = (const float*)d_in[8];
    float* out = (float*)d_out;

    k1_reduce_topk<<<T_ / TK_, 256>>>(x, w1, b1, g1, bt1);
    k2_expand<<<B_ * POOL_, DIM_>>>(w2, b2, g2, bt2);
    k3_gather<<<(B_ * T_ * K_) / 64, 512>>>(out);
}

// round 14
// speedup vs baseline: 1.1163x; 1.0522x over previous
#include <cuda_runtime.h>
#include <cstdint>

#define B_    4
#define T_    1024
#define DIM_  512
#define POOL_ 64
#define K_    50

// Scratch (device globals: allocation-free per harness rules)
__device__ __align__(16) float g_y[B_ * POOL_ * POOL_];   // y[b][t<64][p]
__device__ int   g_idx[T_ * K_];                          // top-50 indices per t
__device__ __align__(16) float g_z[B_ * POOL_ * DIM_];    // z[b][j][d]

// packed fp32x2 ops (Blackwell FFMA2 — only reachable via PTX)
#define FMA2(d, a, b) \
    asm("fma.rn.f32x2 %0, %1, %2, %3;" : "=l"(d) : "l"(a), "l"(b), "l"(d))
#define ADD2(d, a, b) \
    asm("add.rn.f32x2 %0, %1, %2;" : "=l"(d) : "l"(a), "l"(b))
#define UNPACK2(lo, hi, v) \
    asm("mov.b64 {%0, %1}, %2;" : "=f"(lo), "=f"(hi) : "l"(v))
#define LDS_V2U64(a0, a1, addr) \
    asm("ld.shared.v2.b64 {%0, %1}, [%2];" : "=l"(a0), "=l"(a1) : "r"(addr))

// ---------------------------------------------------------------------------
// Kernel 1: ONE token per block, block = 128, grid = 1024.
// Rationale: at one wave, kernel time == per-block critical path; smaller
// blocks halve that path and double independent chains per SM (~7 blocks/SM).
// f32x2 lanes = POOL PAIRS; x staged lane-duplicated in smem.
// Thread (dc=tid>>4 in [0,8), pg=tid&15): pools pg*4..pg*4+3, 4 batches,
// dims [dc*64, dc*64+64). Butterfly over dc-pairs + 4-warp smem reduce,
// LN + stable top-50 tail on first 64 threads.
// ---------------------------------------------------------------------------
__global__ __launch_bounds__(128, 8) void k1_reduce_topk(
        const float* __restrict__ x,
        const float* __restrict__ w1,
        const float* __restrict__ b1,
        const float* __restrict__ g1,
        const float* __restrict__ bt1) {
    __shared__ __align__(16) float2 xs2[B_ * DIM_];       // 16KB dup x
    __shared__ float partial[4 * B_ * POOL_];             // 4KB (4 warps)
    __shared__ float sv[POOL_];
    __shared__ float wsum[2][B_], wsq[2][B_];

    const int t   = blockIdx.x;
    const int tid = threadIdx.x;
    const int pg  = tid & 15;    // pool group: pools pg*4 .. pg*4+3
    const int dc  = tid >> 4;    // dim chunk: dims dc*64 .. dc*64+63

    uint32_t sx;
    asm("{ .reg .u64 tt; cvta.to.shared.u64 tt, %1; cvt.u32.u64 %0, tt; }"
        : "=r"(sx) : "l"(xs2));

    // ---- phase 1: load x row per batch, lane-duplicated (4 float4/thread) ----
    #pragma unroll
    for (int i = tid; i < B_ * (DIM_ / 4); i += 128) {
        int b = i >> 7, j = i & 127;
        float4 v = reinterpret_cast<const float4*>(
            x + ((size_t)b * T_ + t) * DIM_)[j];
        float2* d = xs2 + b * DIM_ + j * 4;
        d[0] = make_float2(v.x, v.x);
        d[1] = make_float2(v.y, v.y);
        d[2] = make_float2(v.z, v.z);
        d[3] = make_float2(v.w, v.w);
    }
    __syncthreads();

    // ---- main loop: 64 dims x 4 batches x 2 pool-pairs per thread ----
    unsigned long long acc[B_][2] = {};
    const ulonglong2* wp = reinterpret_cast<const ulonglong2*>(w1)
                           + (size_t)(dc * 64) * 16 + pg;   // dim row = 16 u64x2

    #pragma unroll 4
    for (int d2 = 0; d2 < 32; d2++) {
        ulonglong2 wd0 = __ldg(wp + d2 * 32);        // dim dc*64 + 2*d2
        ulonglong2 wd1 = __ldg(wp + d2 * 32 + 16);   // dim +1
        const uint32_t a = sx + (uint32_t)((dc * 64 + d2 * 2) * 8);
        #pragma unroll
        for (int b = 0; b < B_; b++) {
            unsigned long long xv0, xv1;
            LDS_V2U64(xv0, xv1, a + (uint32_t)(b * DIM_ * 8));
            FMA2(acc[b][0], xv0, wd0.x);
            FMA2(acc[b][1], xv0, wd0.y);
            FMA2(acc[b][0], xv1, wd1.x);
            FMA2(acc[b][1], xv1, wd1.y);
        }
    }

    // ---- reduce over dc: butterfly (dc pairs via tid bit 4), then smem ----
    #pragma unroll
    for (int b = 0; b < B_; b++) {
        #pragma unroll
        for (int pr = 0; pr < 2; pr++) {
            unsigned long long o = __shfl_xor_sync(0xffffffffu, acc[b][pr], 16);
            ADD2(acc[b][pr], acc[b][pr], o);
        }
    }
    __syncthreads();   // x reads done (partial is a separate buffer)

    if ((tid & 16) == 0) {          // one lane per (warp, pg)
        const int w = tid >> 5;     // 0..3: dims [w*128, (w+1)*128)
        #pragma unroll
        for (int b = 0; b < B_; b++) {
            #pragma unroll
            for (int pr = 0; pr < 2; pr++) {
                float lo, hi;
                UNPACK2(lo, hi, acc[b][pr]);
                partial[w * 256 + b * 64 + pg * 4 + pr * 2 + 0] = lo;
                partial[w * 256 + b * 64 + pg * 4 + pr * 2 + 1] = hi;
            }
        }
    }
    __syncthreads();

    // ---- tail on first 64 threads (warps 0,1): pp = tid ----
    if (tid < POOL_) {
        const int pp = tid;
        const float bias = b1[pp];

        float vv[B_];
        #pragma unroll
        for (int b = 0; b < B_; b++) {
            float a = bias;
            #pragma unroll
            for (int w = 0; w < 4; w++)
                a += partial[w * 256 + b * 64 + pp];
            vv[b] = fmaxf(a, 0.f);
        }

        float s[B_], q[B_];
        #pragma unroll
        for (int b = 0; b < B_; b++) { s[b] = vv[b]; q[b] = vv[b] * vv[b]; }
        #pragma unroll
        for (int off = 16; off > 0; off >>= 1) {
            #pragma unroll
            for (int b = 0; b < B_; b++) {
                s[b] += __shfl_xor_sync(0xffffffffu, s[b], off);
                q[b] += __shfl_xor_sync(0xffffffffu, q[b], off);
            }
        }
        const int w = tid >> 5;   // 0 or 1
        if ((tid & 31) == 0) {
            #pragma unroll
            for (int b = 0; b < B_; b++) { wsum[w][b] = s[b]; wsq[w][b] = q[b]; }
        }
        __syncwarp();
        asm volatile("bar.sync 1, 64;" ::: "memory");

        const float gp = g1[pp], bp = bt1[pp];
        float ysum = 0.f;
        float yv[B_];
        #pragma unroll
        for (int b = 0; b < B_; b++) {
            float S = wsum[0][b] + wsum[1][b];
            float Q = wsq[0][b]  + wsq[1][b];
            float m   = S * (1.f / POOL_);
            float var = Q * (1.f / POOL_) - m * m;
            float r   = rsqrtf(var + 1e-5f);
            yv[b] = (vv[b] - m) * r * gp + bp;
            ysum += yv[b];
        }

        if (t < POOL_) {
            #pragma unroll
            for (int b = 0; b < B_; b++)
                g_y[(b * POOL_ + t) * POOL_ + pp] = yv[b];
        }

        sv[pp] = ysum;
        asm volatile("bar.sync 1, 64;" ::: "memory");

        const float mine = ysum;
        int rank = 0;
        #pragma unroll
        for (int j = 0; j < POOL_; j++) {
            float o = sv[j];
            rank += (o > mine) || ((o == mine) && (j < pp));
        }
        if (rank < K_) g_idx[t * K_ + rank] = pp;
    }
}

// ---------------------------------------------------------------------------
// Kernel 2: z[b,j,:] = LN(relu(y[b,j,:] @ w2 + b2))   (256 distinct rows)
// grid = B_*POOL_, block = 512
// ---------------------------------------------------------------------------
__global__ void k2_expand(const float* __restrict__ w2,
                          const float* __restrict__ b2,
                          const float* __restrict__ g2,
                          const float* __restrict__ bt2) {
    const int bj = blockIdx.x;
    const int d  = threadIdx.x;

    __shared__ float yr[POOL_];
    if (d < POOL_) yr[d] = g_y[bj * POOL_ + d];
    __syncthreads();

    float acc = b2[d];
    #pragma unroll
    for (int p = 0; p < POOL_; p++)
        acc += yr[p] * w2[p * DIM_ + d];

    float v = fmaxf(acc, 0.f);

    float s = v, q = v * v;
    #pragma unroll
    for (int off = 16; off > 0; off >>= 1) {
        s += __shfl_xor_sync(0xffffffffu, s, off);
        q += __shfl_xor_sync(0xffffffffu, q, off);
    }
    __shared__ float ps[16], pq[16];
    const int w = d >> 5;
    if ((d & 31) == 0) { ps[w] = s; pq[w] = q; }
    __syncthreads();
    float S = 0.f, Q = 0.f;
    #pragma unroll
    for (int i = 0; i < 16; i++) { S += ps[i]; Q += pq[i]; }

    float m   = S * (1.f / DIM_);
    float var = Q * (1.f / DIM_) - m * m;
    g_z[bj * DIM_ + d] = (v - m) * rsqrtf(var + 1e-5f) * g2[d] + bt2[d];
}

// ---------------------------------------------------------------------------
// Kernel 3: out[b,t,k,:] = z[b, idx[t,k], :]  — the 419 MB write stream.
// Round-5 configuration (__ldg reads, __stcs streaming stores). At the
// HBM-write roofline.
// ---------------------------------------------------------------------------
__global__ void k3_gather(float* __restrict__ out) {
    const int warp = threadIdx.x >> 5;
    const int lane = threadIdx.x & 31;
    const unsigned base = blockIdx.x * 64u;

    #pragma unroll
    for (int i = 0; i < 4; i++) {
        unsigned r   = base + warp + i * 16;
        unsigned b   = r / (unsigned)(T_ * K_);
        unsigned rem = r - b * (unsigned)(T_ * K_);
        unsigned t   = rem / K_;
        unsigned k   = rem - t * K_;
        int j = g_idx[t * K_ + k];

        const float4* src = reinterpret_cast<const float4*>(g_z)
                            + (size_t)(b * POOL_ + j) * (DIM_ / 4);
        float4* dst = reinterpret_cast<float4*>(out)
                      + (size_t)r * (DIM_ / 4);
        #pragma unroll
        for (int cc = 0; cc < 4; cc++) {
            float4 v = __ldg(src + lane + 32 * cc);
            __stcs(dst + lane + 32 * cc, v);
        }
    }
}

// ---------------------------------------------------------------------------
extern "C" void kernel_launch(void* const* d_in, const int* in_sizes, int n_in,
                              void* d_out, int out_size) {
    const float* x   = (const float*)d_in[0];
    const float* w1  = (const float*)d_in[1];
    const float* b1  = (const float*)d_in[2];
    const float* g1  = (const float*)d_in[3];
    const float* bt1 = (const float*)d_in[4];
    const float* w2  = (const float*)d_in[5];
    const float* b2  = (const float*)d_in[6];
    const float* g2  = (const float*)d_in[7];
    const float* bt2 = (const float*)d_in[8];
    float* out = (float*)d_out;

    k1_reduce_topk<<<T_, 128>>>(x, w1, b1, g1, bt1);
    k2_expand<<<B_ * POOL_, DIM_>>>(w2, b2, g2, bt2);
    k3_gather<<<(B_ * T_ * K_) / 64, 512>>>(out);
}